// round 13
// baseline (speedup 1.0000x reference)
#include <cuda_runtime.h>
#include <math.h>
#include <stdint.h>

// Problem constants
#define S_LEN   2048
#define DMODEL  2048
#define NHEADS  16
#define DKH     128
#define BATCH   4
#define BHN     (BATCH * NHEADS)   // 64
#define E3      (3 * DMODEL)       // 6144
#define MROWS   (BATCH * S_LEN)    // 8192
#define KDIM    DMODEL             // 2048

// ---------------------------------------------------------------------------
// Scratch (static device globals: allocation-free rule)
// ---------------------------------------------------------------------------
__device__ __align__(256) float g_q[BHN * S_LEN * DKH];
__device__ __align__(256) float g_k[BHN * S_LEN * DKH];
__device__ __align__(256) float g_v[BHN * S_LEN * DKH];
__device__ __align__(256) float g_attn[BATCH * S_LEN * DMODEL];
__device__ __align__(256) float g_cos[S_LEN * (DKH / 2)];
__device__ __align__(256) float g_sin[S_LEN * (DKH / 2)];

// ---------------------------------------------------------------------------
// RoPE tables (fp64 for accuracy)
// ---------------------------------------------------------------------------
__global__ void rope_tables_kernel() {
    int idx = blockIdx.x * blockDim.x + threadIdx.x;
    if (idx >= S_LEN * (DKH / 2)) return;
    int i = idx % (DKH / 2);
    int s = idx / (DKH / 2);
    double inv = exp(-((double)(2 * i) / (double)DKH) * log(10000.0));
    double ang = (double)s * inv;
    g_cos[idx] = (float)cos(ang);
    g_sin[idx] = (float)sin(ang);
}

// ---------------------------------------------------------------------------
// FFMA SGEMM  C[M,N] = A[M,K] * B[N,K]^T
// k-tile 16, double-buffered smem: ONE barrier per chunk (128 total),
// register prefetch, conflict-free fragment reads (R11 mapping).
// MODE 1: QKV -> scatter g_q/g_k/g_v with RoPE fused on q,k parts.
// MODE 2: out-proj (A = g_attn) -> row-major C.
// ---------------------------------------------------------------------------
template <int MODE>
__global__ void __launch_bounds__(256, 2)
sgemm_nt(const float* __restrict__ A, const float* __restrict__ Bw,
         float* __restrict__ C, int M, int N, int K) {
    __shared__ float As[2][16 * 132];
    __shared__ float Bs[2][16 * 132];

    const int bm = blockIdx.y << 7;
    const int bn = blockIdx.x << 7;
    const int tid = threadIdx.x;
    const int tx = tid & 15, ty = tid >> 4;

    const float* Aarr = (MODE == 2) ? g_attn : A;
    const int lr = tid >> 1;            // row 0..127
    const int lk = (tid & 1) << 2;      // k offset 0 or 4
    const float* Ap = Aarr + (size_t)(bm + lr) * K + lk;
    const float* Bp = Bw + (size_t)(bn + lr) * K + lk;

    float acc[8][8];
#pragma unroll
    for (int i = 0; i < 8; i++)
#pragma unroll
        for (int j = 0; j < 8; j++) acc[i][j] = 0.0f;

    // prefetch chunk 0: k positions lk..lk+3 and lk+8..lk+11
    float4 a0 = *(const float4*)Ap;
    float4 a1 = *(const float4*)(Ap + 8);
    float4 b0 = *(const float4*)Bp;
    float4 b1 = *(const float4*)(Bp + 8);

    const int NCH = K >> 4;   // 128
    for (int c = 0; c < NCH; c++) {
        const int buf = c & 1;
        float* as = As[buf];
        float* bs = Bs[buf];
        as[(lk + 0) * 132 + lr] = a0.x;
        as[(lk + 1) * 132 + lr] = a0.y;
        as[(lk + 2) * 132 + lr] = a0.z;
        as[(lk + 3) * 132 + lr] = a0.w;
        as[(lk + 8) * 132 + lr] = a1.x;
        as[(lk + 9) * 132 + lr] = a1.y;
        as[(lk + 10) * 132 + lr] = a1.z;
        as[(lk + 11) * 132 + lr] = a1.w;
        bs[(lk + 0) * 132 + lr] = b0.x;
        bs[(lk + 1) * 132 + lr] = b0.y;
        bs[(lk + 2) * 132 + lr] = b0.z;
        bs[(lk + 3) * 132 + lr] = b0.w;
        bs[(lk + 8) * 132 + lr] = b1.x;
        bs[(lk + 9) * 132 + lr] = b1.y;
        bs[(lk + 10) * 132 + lr] = b1.z;
        bs[(lk + 11) * 132 + lr] = b1.w;
        __syncthreads();

        if (c + 1 < NCH) {
            const int kb = (c + 1) << 4;
            a0 = *(const float4*)(Ap + kb);
            a1 = *(const float4*)(Ap + kb + 8);
            b0 = *(const float4*)(Bp + kb);
            b1 = *(const float4*)(Bp + kb + 8);
        }

#pragma unroll
        for (int kk = 0; kk < 16; kk++) {
            float a[8], b[8];
            *(float4*)(a)     = *(const float4*)&as[kk * 132 + (ty << 3)];
            *(float4*)(a + 4) = *(const float4*)&as[kk * 132 + (ty << 3) + 4];
            // conflict-free: 16B stride across the 16 phase lanes
            *(float4*)(b)     = *(const float4*)&bs[kk * 132 + (tx << 2)];
            *(float4*)(b + 4) = *(const float4*)&bs[kk * 132 + (tx << 2) + 64];
#pragma unroll
            for (int i = 0; i < 8; i++)
#pragma unroll
                for (int j = 0; j < 8; j++)
                    acc[i][j] = fmaf(a[i], b[j], acc[i][j]);
        }
    }

    const int cA = tx << 2;        // cols cA..cA+3 within the 128-wide n-tile
    const int cB = cA + 64;        // cols cB..cB+3
    if (MODE == 2) {
#pragma unroll
        for (int i = 0; i < 8; i++) {
            float* crow = C + (size_t)(bm + (ty << 3) + i) * N + bn;
            *(float4*)(crow + cA) = make_float4(acc[i][0], acc[i][1], acc[i][2], acc[i][3]);
            *(float4*)(crow + cB) = make_float4(acc[i][4], acc[i][5], acc[i][6], acc[i][7]);
        }
    } else {
        const int part = bn >> 11;
        const int h = (bn >> 7) & 15;
        float* dst = (part == 0) ? g_q : ((part == 1) ? g_k : g_v);
#pragma unroll
        for (int i = 0; i < 8; i++) {
            int m = bm + (ty << 3) + i;
            int b = m >> 11;
            int s = m & (S_LEN - 1);
            if (part < 2) {
                int pb = (s << 6) + (cA >> 1);
#pragma unroll
                for (int t = 0; t < 2; t++) {
                    float cs = g_cos[pb + t], sn = g_sin[pb + t];
                    float e = acc[i][2 * t], o = acc[i][2 * t + 1];
                    acc[i][2 * t]     = e * cs - o * sn;
                    acc[i][2 * t + 1] = e * sn + o * cs;
                    float cs2 = g_cos[pb + 32 + t], sn2 = g_sin[pb + 32 + t];
                    float e2 = acc[i][4 + 2 * t], o2 = acc[i][5 + 2 * t];
                    acc[i][4 + 2 * t] = e2 * cs2 - o2 * sn2;
                    acc[i][5 + 2 * t] = e2 * sn2 + o2 * cs2;
                }
            }
            float* row = dst + (((size_t)(b * NHEADS + h) * S_LEN + s) << 7);
            *(float4*)(row + cA) = make_float4(acc[i][0], acc[i][1], acc[i][2], acc[i][3]);
            *(float4*)(row + cB) = make_float4(acc[i][4], acc[i][5], acc[i][6], acc[i][7]);
        }
    }
}

// ---------------------------------------------------------------------------
// Flash attention (causal, fp32) -> g_attn.   (R12-validated)
// Shared K/V smem buffer -> 83 KB -> 2 CTAs/SM.  Conflict-free mappings.
// ---------------------------------------------------------------------------
#define ATTN_SMEM_FLOATS (2 * 64 * 132 + 64 * 68)   // Q + KV + P = 21248

__global__ void __launch_bounds__(256, 2)
attn_kernel() {
    extern __shared__ float smf[];
    float* Qs  = smf;
    float* KVs = smf + 64 * 132;
    float* Ps  = smf + 2 * 64 * 132;

    const int qt = gridDim.x - 1 - blockIdx.x;   // heavy tiles first
    const int bh = blockIdx.y;
    const size_t base = (size_t)bh * S_LEN * DKH;
    const float* qp = g_q + base + ((size_t)qt << 6) * DKH;
    const float* kp = g_k + base;
    const float* vp = g_v + base;

    const int tid = threadIdx.x;
    const int tx = tid & 15, ty = tid >> 4;
    const int r0 = ty << 2;
    const int cA = tx << 2;
    const int cB = cA + 64;

    const float scale = 0.08838834764831845f;
    for (int i = tid; i < 64 * 32; i += 256) {
        int r = i >> 5, c4 = (i & 31) << 2;
        float4 v = *(const float4*)&qp[r * 128 + c4];
        Qs[r * 132 + c4 + 0] = v.x * scale;
        Qs[r * 132 + c4 + 1] = v.y * scale;
        Qs[r * 132 + c4 + 2] = v.z * scale;
        Qs[r * 132 + c4 + 3] = v.w * scale;
    }

    float o[4][8];
#pragma unroll
    for (int i = 0; i < 4; i++)
#pragma unroll
        for (int c = 0; c < 8; c++) o[i][c] = 0.0f;
    float mi[4] = {-INFINITY, -INFINITY, -INFINITY, -INFINITY};
    float li[4] = {0.0f, 0.0f, 0.0f, 0.0f};

    for (int j = 0; j <= qt; j++) {
        __syncthreads();
        const float* kt = kp + ((size_t)j << 6) * DKH;
        for (int i = tid; i < 64 * 32; i += 256) {
            int r = i >> 5, c4 = (i & 31) << 2;
            *(float4*)&KVs[r * 132 + c4] = *(const float4*)&kt[r * 128 + c4];
        }
        __syncthreads();

        float s[4][4];
#pragma unroll
        for (int i = 0; i < 4; i++)
#pragma unroll
            for (int ii = 0; ii < 4; ii++) s[i][ii] = 0.0f;

#pragma unroll 4
        for (int k4 = 0; k4 < 32; k4++) {
            float q[4][4], kv[4][4];
#pragma unroll
            for (int i = 0; i < 4; i++)
                *(float4*)q[i] = *(const float4*)&Qs[(r0 + i) * 132 + (k4 << 2)];
#pragma unroll
            for (int ii = 0; ii < 4; ii++)
                *(float4*)kv[ii] = *(const float4*)&KVs[(tx + (ii << 4)) * 132 + (k4 << 2)];
#pragma unroll
            for (int i = 0; i < 4; i++)
#pragma unroll
                for (int ii = 0; ii < 4; ii++)
#pragma unroll
                    for (int t = 0; t < 4; t++)
                        s[i][ii] = fmaf(q[i][t], kv[ii][t], s[i][ii]);
        }

#pragma unroll
        for (int i = 0; i < 4; i++) {
            float sv[4];
#pragma unroll
            for (int ii = 0; ii < 4; ii++) {
                float v = s[i][ii];
                if (j == qt && (tx + (ii << 4)) > (r0 + i)) v = -1e30f;
                sv[ii] = v;
            }
            float rm = fmaxf(fmaxf(sv[0], sv[1]), fmaxf(sv[2], sv[3]));
#pragma unroll
            for (int off = 8; off >= 1; off >>= 1)
                rm = fmaxf(rm, __shfl_xor_sync(0xffffffffu, rm, off));
            float mn = fmaxf(mi[i], rm);
            float al = __expf(mi[i] - mn);
            float rs = 0.0f;
#pragma unroll
            for (int ii = 0; ii < 4; ii++) {
                float p = __expf(sv[ii] - mn);
                sv[ii] = p;
                rs += p;
            }
#pragma unroll
            for (int off = 8; off >= 1; off >>= 1)
                rs += __shfl_xor_sync(0xffffffffu, rs, off);
            li[i] = li[i] * al + rs;
            mi[i] = mn;
#pragma unroll
            for (int c = 0; c < 8; c++) o[i][c] *= al;
#pragma unroll
            for (int ii = 0; ii < 4; ii++)
                Ps[(r0 + i) * 68 + tx + (ii << 4)] = sv[ii];
        }

        __syncthreads();
        const float* vt = vp + ((size_t)j << 6) * DKH;
        for (int i = tid; i < 64 * 32; i += 256) {
            int r = i >> 5, c4 = (i & 31) << 2;
            *(float4*)&KVs[r * 132 + c4] = *(const float4*)&vt[r * 128 + c4];
        }
        __syncthreads();

#pragma unroll 4
        for (int jj4 = 0; jj4 < 16; jj4++) {
            float p[4][4];
#pragma unroll
            for (int i = 0; i < 4; i++)
                *(float4*)p[i] = *(const float4*)&Ps[(r0 + i) * 68 + (jj4 << 2)];
#pragma unroll
            for (int t = 0; t < 4; t++) {
                int jj = (jj4 << 2) + t;
                float v[8];
                *(float4*)(v)     = *(const float4*)&KVs[jj * 132 + cA];
                *(float4*)(v + 4) = *(const float4*)&KVs[jj * 132 + cB];
#pragma unroll
                for (int i = 0; i < 4; i++)
#pragma unroll
                    for (int c = 0; c < 8; c++)
                        o[i][c] = fmaf(p[i][t], v[c], o[i][c]);
            }
        }
    }

    const int b = bh >> 4, h = bh & 15;
#pragma unroll
    for (int i = 0; i < 4; i++) {
        float inv = 1.0f / li[i];
        int srow = (qt << 6) + r0 + i;
        float* orow = g_attn + (((size_t)(b * S_LEN + srow)) << 11) + (h << 7);
        *(float4*)(orow + cA) = make_float4(o[i][0] * inv, o[i][1] * inv,
                                            o[i][2] * inv, o[i][3] * inv);
        *(float4*)(orow + cB) = make_float4(o[i][4] * inv, o[i][5] * inv,
                                            o[i][6] * inv, o[i][7] * inv);
    }
}

// ---------------------------------------------------------------------------
// kernel_launch
// ---------------------------------------------------------------------------
extern "C" void kernel_launch(void* const* d_in, const int* in_sizes, int n_in,
                              void* d_out, int out_size) {
    const float* x     = (const float*)d_in[0];
    const float* w_qkv = (const float*)d_in[1];
    const float* w_out = (const float*)d_in[2];
    float* out = (float*)d_out;

    cudaFuncSetAttribute(attn_kernel, cudaFuncAttributeMaxDynamicSharedMemorySize,
                         ATTN_SMEM_FLOATS * (int)sizeof(float));

    // RoPE tables (consumed by the QKV epilogue)
    rope_tables_kernel<<<(S_LEN * (DKH / 2) + 255) / 256, 256>>>();

    // QKV projection with fused RoPE, scatter into g_q/g_k/g_v
    sgemm_nt<1><<<dim3(E3 / 128, MROWS / 128), 256>>>(x, w_qkv, nullptr,
                                                      MROWS, E3, KDIM);

    // causal flash attention -> g_attn (2 CTAs/SM)
    attn_kernel<<<dim3(S_LEN / 64, BHN), 256,
                  ATTN_SMEM_FLOATS * (int)sizeof(float)>>>();

    // output projection
    sgemm_nt<2><<<dim3(DMODEL / 128, MROWS / 128), 256>>>(nullptr, w_out, out,
                                                          MROWS, DMODEL, KDIM);
}

// round 15
// speedup vs baseline: 1.0463x; 1.0463x over previous
#include <cuda_runtime.h>
#include <math.h>
#include <stdint.h>

// Problem constants
#define S_LEN   2048
#define DMODEL  2048
#define NHEADS  16
#define DKH     128
#define BATCH   4
#define BHN     (BATCH * NHEADS)   // 64
#define E3      (3 * DMODEL)       // 6144
#define MROWS   (BATCH * S_LEN)    // 8192
#define KDIM    DMODEL             // 2048

// ---------------------------------------------------------------------------
// Scratch (static device globals: allocation-free rule)
// ---------------------------------------------------------------------------
__device__ __align__(256) float g_q[BHN * S_LEN * DKH];
__device__ __align__(256) float g_k[BHN * S_LEN * DKH];
__device__ __align__(256) float g_v[BHN * S_LEN * DKH];
__device__ __align__(256) float g_attn[BATCH * S_LEN * DMODEL];
__device__ __align__(256) float g_cos[S_LEN * (DKH / 2)];
__device__ __align__(256) float g_sin[S_LEN * (DKH / 2)];

// ---------------------------------------------------------------------------
// helpers
// ---------------------------------------------------------------------------
__device__ __forceinline__ uint32_t smem_to_u32(const void* p) {
    uint32_t a;
    asm("{ .reg .u64 t; cvta.to.shared.u64 t, %1; cvt.u32.u64 %0, t; }" : "=r"(a) : "l"(p));
    return a;
}
__device__ __forceinline__ void cp_async16(uint32_t smem, const void* g) {
    asm volatile("cp.async.cg.shared.global [%0], [%1], 16;" :: "r"(smem), "l"(g) : "memory");
}
#define CP_COMMIT() asm volatile("cp.async.commit_group;" ::: "memory")
#define CP_WAIT(n)  asm volatile("cp.async.wait_group %0;" :: "n"(n) : "memory")

// ---------------------------------------------------------------------------
// RoPE tables (fp64 for accuracy)
// ---------------------------------------------------------------------------
__global__ void rope_tables_kernel() {
    int idx = blockIdx.x * blockDim.x + threadIdx.x;
    if (idx >= S_LEN * (DKH / 2)) return;
    int i = idx % (DKH / 2);
    int s = idx / (DKH / 2);
    double inv = exp(-((double)(2 * i) / (double)DKH) * log(10000.0));
    double ang = (double)s * inv;
    g_cos[idx] = (float)cos(ang);
    g_sin[idx] = (float)sin(ang);
}

// ---------------------------------------------------------------------------
// FFMA SGEMM  C[M,N] = A[M,K] * B[N,K]^T   (R12-validated, k8, conflict-free)
// MODE 1: QKV -> scatter g_q/g_k/g_v with RoPE fused on q,k parts.
// MODE 2: out-proj (A = g_attn) -> row-major C.
// ---------------------------------------------------------------------------
template <int MODE>
__global__ void __launch_bounds__(256, 2)
sgemm_nt(const float* __restrict__ A, const float* __restrict__ Bw,
         float* __restrict__ C, int M, int N, int K) {
    __shared__ float As[8 * 132];
    __shared__ float Bs[8 * 132];

    const int bm = blockIdx.y << 7;
    const int bn = blockIdx.x << 7;
    const int tid = threadIdx.x;
    const int tx = tid & 15, ty = tid >> 4;

    const float* Aarr = (MODE == 2) ? g_attn : A;
    const int lr = tid >> 1;
    const int lk = (tid & 1) << 2;
    const float* Ap = Aarr + (size_t)(bm + lr) * K + lk;
    const float* Bp = Bw + (size_t)(bn + lr) * K + lk;

    float acc[8][8];
#pragma unroll
    for (int i = 0; i < 8; i++)
#pragma unroll
        for (int j = 0; j < 8; j++) acc[i][j] = 0.0f;

    float4 af = *(const float4*)Ap;
    float4 bf = *(const float4*)Bp;

    for (int k0 = 0; k0 < K; k0 += 8) {
        __syncthreads();
        As[(lk + 0) * 132 + lr] = af.x;
        As[(lk + 1) * 132 + lr] = af.y;
        As[(lk + 2) * 132 + lr] = af.z;
        As[(lk + 3) * 132 + lr] = af.w;
        Bs[(lk + 0) * 132 + lr] = bf.x;
        Bs[(lk + 1) * 132 + lr] = bf.y;
        Bs[(lk + 2) * 132 + lr] = bf.z;
        Bs[(lk + 3) * 132 + lr] = bf.w;
        __syncthreads();
        if (k0 + 8 < K) {
            af = *(const float4*)(Ap + k0 + 8);
            bf = *(const float4*)(Bp + k0 + 8);
        }
#pragma unroll
        for (int kk = 0; kk < 8; kk++) {
            float a[8], b[8];
            *(float4*)(a)     = *(const float4*)&As[kk * 132 + (ty << 3)];
            *(float4*)(a + 4) = *(const float4*)&As[kk * 132 + (ty << 3) + 4];
            *(float4*)(b)     = *(const float4*)&Bs[kk * 132 + (tx << 2)];
            *(float4*)(b + 4) = *(const float4*)&Bs[kk * 132 + (tx << 2) + 64];
#pragma unroll
            for (int i = 0; i < 8; i++)
#pragma unroll
                for (int j = 0; j < 8; j++)
                    acc[i][j] = fmaf(a[i], b[j], acc[i][j]);
        }
    }

    const int cA = tx << 2;
    const int cB = cA + 64;
    if (MODE == 2) {
#pragma unroll
        for (int i = 0; i < 8; i++) {
            float* crow = C + (size_t)(bm + (ty << 3) + i) * N + bn;
            *(float4*)(crow + cA) = make_float4(acc[i][0], acc[i][1], acc[i][2], acc[i][3]);
            *(float4*)(crow + cB) = make_float4(acc[i][4], acc[i][5], acc[i][6], acc[i][7]);
        }
    } else {
        const int part = bn >> 11;
        const int h = (bn >> 7) & 15;
        float* dst = (part == 0) ? g_q : ((part == 1) ? g_k : g_v);
#pragma unroll
        for (int i = 0; i < 8; i++) {
            int m = bm + (ty << 3) + i;
            int b = m >> 11;
            int s = m & (S_LEN - 1);
            if (part < 2) {
                int pb = (s << 6) + (cA >> 1);
#pragma unroll
                for (int t = 0; t < 2; t++) {
                    float cs = g_cos[pb + t], sn = g_sin[pb + t];
                    float e = acc[i][2 * t], o = acc[i][2 * t + 1];
                    acc[i][2 * t]     = e * cs - o * sn;
                    acc[i][2 * t + 1] = e * sn + o * cs;
                    float cs2 = g_cos[pb + 32 + t], sn2 = g_sin[pb + 32 + t];
                    float e2 = acc[i][4 + 2 * t], o2 = acc[i][5 + 2 * t];
                    acc[i][4 + 2 * t] = e2 * cs2 - o2 * sn2;
                    acc[i][5 + 2 * t] = e2 * sn2 + o2 * cs2;
                }
            }
            float* row = dst + (((size_t)(b * NHEADS + h) * S_LEN + s) << 7);
            *(float4*)(row + cA) = make_float4(acc[i][0], acc[i][1], acc[i][2], acc[i][3]);
            *(float4*)(row + cB) = make_float4(acc[i][4], acc[i][5], acc[i][6], acc[i][7]);
        }
    }
}

// ---------------------------------------------------------------------------
// Flash attention (causal, fp32) -> g_attn.
// cp.async pipelined K/V (K(j+1) and V(j) prefetch under compute),
// 112 KB smem/CTA -> 2 CTAs/SM.
// Pitches: Q 128, K 128 (XOR-swizzled granules), V 128, P 64.
// K swizzle: element (r,c) stored at granule (c>>2) ^ (r&7)   (16B granules)
//   -> conflict-free QK reads at pitch 128; store-side XOR is per-thread const.
// Q pre-scaled; heavy tiles first.
// ---------------------------------------------------------------------------
#define QP 128
#define KP 128
#define VP 128
#define PP 64
#define OFF_K  (64 * QP)
#define OFF_V  (OFF_K + 64 * KP)
#define OFF_P  (OFF_V + 64 * VP)
#define ATTN_SMEM_FLOATS (OFF_P + 64 * PP)   // 28672 floats = 112 KB

__global__ void __launch_bounds__(256, 2)
attn_kernel() {
    extern __shared__ float smf[];
    float* Qs = smf;
    float* Ks = smf + OFF_K;
    float* Vs = smf + OFF_V;
    float* Ps = smf + OFF_P;

    const int qt = gridDim.x - 1 - blockIdx.x;   // heavy tiles first
    const int bh = blockIdx.y;
    const size_t base = (size_t)bh * S_LEN * DKH;
    const float* qp = g_q + base + ((size_t)qt << 6) * DKH;
    const char* kp = (const char*)(g_k + base);
    const char* vp = (const char*)(g_v + base);

    const int tid = threadIdx.x;
    const int tx = tid & 15, ty = tid >> 4;
    const int r0 = ty << 2;
    const int cA = tx << 2;
    const int cB = cA + 64;
    const int sx = tx & 7;            // K read swizzle constant

    const uint32_t sb = smem_to_u32(smf);
    const uint32_t kaddr = sb + OFF_K * 4;
    const uint32_t vaddr = sb + OFF_V * 4;

    // cp.async slots: row r = lr + 8p (r&7 == lr), granule g0 = tid&31
    const int lr = tid >> 5;                       // 0..7 (= warp id)
    const int g0 = tid & 31;
    const int kg = (g0 & ~7) | ((g0 ^ lr) & 7);    // swizzled K granule (const)
    const uint32_t koff = (uint32_t)(kg << 4);
    const uint32_t voff = (uint32_t)(g0 << 4);
    const uint32_t gsrc = (uint32_t)(g0 << 4);

    // issue K(0)
#pragma unroll
    for (int p = 0; p < 8; p++) {
        int r = lr + (p << 3);
        cp_async16(kaddr + r * 512 + koff, kp + r * 512 + gsrc);
    }
    CP_COMMIT();

    // Q tile load, pre-scaled by 1/sqrt(dk)
    const float scale = 0.08838834764831845f;
    for (int i = tid; i < 64 * 32; i += 256) {
        int r = i >> 5, c4 = (i & 31) << 2;
        float4 v = *(const float4*)&qp[r * 128 + c4];
        Qs[r * QP + c4 + 0] = v.x * scale;
        Qs[r * QP + c4 + 1] = v.y * scale;
        Qs[r * QP + c4 + 2] = v.z * scale;
        Qs[r * QP + c4 + 3] = v.w * scale;
    }

    float o[4][8];
#pragma unroll
    for (int i = 0; i < 4; i++)
#pragma unroll
        for (int c = 0; c < 8; c++) o[i][c] = 0.0f;
    float mi[4] = {-INFINITY, -INFINITY, -INFINITY, -INFINITY};
    float li[4] = {0.0f, 0.0f, 0.0f, 0.0f};

    for (int j = 0; j <= qt; j++) {
        // V buffer free (PV of j-1 complete): issue V(j)
        __syncthreads();
        {
            const char* vt = vp + ((size_t)j << 15);   // j * 64*128*4
#pragma unroll
            for (int p = 0; p < 8; p++) {
                int r = lr + (p << 3);
                cp_async16(vaddr + r * 512 + voff, vt + r * 512 + gsrc);
            }
            CP_COMMIT();
        }
        CP_WAIT(1);        // K(j) arrived; V(j) may be in flight
        __syncthreads();

        // S = Q * K^T ; thread's score cols: tx + 16*ii (K swizzle-read)
        float s[4][4];
#pragma unroll
        for (int i = 0; i < 4; i++)
#pragma unroll
            for (int ii = 0; ii < 4; ii++) s[i][ii] = 0.0f;

#pragma unroll 4
        for (int k4 = 0; k4 < 32; k4++) {
            const int kc = (k4 ^ sx) << 2;
            float q[4][4], kv[4][4];
#pragma unroll
            for (int i = 0; i < 4; i++)
                *(float4*)q[i] = *(const float4*)&Qs[(r0 + i) * QP + (k4 << 2)];
#pragma unroll
            for (int ii = 0; ii < 4; ii++)
                *(float4*)kv[ii] = *(const float4*)&Ks[(tx + (ii << 4)) * KP + kc];
            // q holds k-positions k4*4..+3 ; kv holds (k4^sx)*4..+3 — mismatch!
            // Fix: use the SAME logical k for both: load q at swizzled position too.
#pragma unroll
            for (int i = 0; i < 4; i++)
#pragma unroll
                for (int ii = 0; ii < 4; ii++)
#pragma unroll
                    for (int t = 0; t < 4; t++)
                        s[i][ii] = fmaf(q[i][t], kv[ii][t], s[i][ii]);
        }

        // online softmax per row
#pragma unroll
        for (int i = 0; i < 4; i++) {
            float sv[4];
#pragma unroll
            for (int ii = 0; ii < 4; ii++) {
                float v = s[i][ii];
                if (j == qt && (tx + (ii << 4)) > (r0 + i)) v = -1e30f;
                sv[ii] = v;
            }
            float rm = fmaxf(fmaxf(sv[0], sv[1]), fmaxf(sv[2], sv[3]));
#pragma unroll
            for (int off = 8; off >= 1; off >>= 1)
                rm = fmaxf(rm, __shfl_xor_sync(0xffffffffu, rm, off));
            float mn = fmaxf(mi[i], rm);
            float al = __expf(mi[i] - mn);
            float rs = 0.0f;
#pragma unroll
            for (int ii = 0; ii < 4; ii++) {
                float p = __expf(sv[ii] - mn);
                sv[ii] = p;
                rs += p;
            }
#pragma unroll
            for (int off = 8; off >= 1; off >>= 1)
                rs += __shfl_xor_sync(0xffffffffu, rs, off);
            li[i] = li[i] * al + rs;
            mi[i] = mn;
#pragma unroll
            for (int c = 0; c < 8; c++) o[i][c] *= al;
#pragma unroll
            for (int ii = 0; ii < 4; ii++)
                Ps[(r0 + i) * PP + tx + (ii << 4)] = sv[ii];
        }

        // K reads + P writes done: issue K(j+1), then wait for V(j)
        __syncthreads();
        if (j < qt) {
            const char* kt = kp + ((size_t)(j + 1) << 15);
#pragma unroll
            for (int p = 0; p < 8; p++) {
                int r = lr + (p << 3);
                cp_async16(kaddr + r * 512 + koff, kt + r * 512 + gsrc);
            }
            CP_COMMIT();
            CP_WAIT(1);    // V(j) arrived; K(j+1) in flight
        } else {
            CP_WAIT(0);    // V(qt) arrived
        }
        __syncthreads();

        // O += P * V ; thread's output cols: cA..cA+3, cB..cB+3
#pragma unroll 4
        for (int jj4 = 0; jj4 < 16; jj4++) {
            float p[4][4];
#pragma unroll
            for (int i = 0; i < 4; i++)
                *(float4*)p[i] = *(const float4*)&Ps[(r0 + i) * PP + (jj4 << 2)];
#pragma unroll
            for (int t = 0; t < 4; t++) {
                int jj = (jj4 << 2) + t;
                float v[8];
                *(float4*)(v)     = *(const float4*)&Vs[jj * VP + cA];
                *(float4*)(v + 4) = *(const float4*)&Vs[jj * VP + cB];
#pragma unroll
                for (int i = 0; i < 4; i++)
#pragma unroll
                    for (int c = 0; c < 8; c++)
                        o[i][c] = fmaf(p[i][t], v[c], o[i][c]);
            }
        }
    }

    // epilogue: normalize, write fp32 to g_attn [B,S,D] with D = h*128+dk
    const int b = bh >> 4, h = bh & 15;
#pragma unroll
    for (int i = 0; i < 4; i++) {
        float inv = 1.0f / li[i];
        int srow = (qt << 6) + r0 + i;
        float* orow = g_attn + (((size_t)(b * S_LEN + srow)) << 11) + (h << 7);
        *(float4*)(orow + cA) = make_float4(o[i][0] * inv, o[i][1] * inv,
                                            o[i][2] * inv, o[i][3] * inv);
        *(float4*)(orow + cB) = make_float4(o[i][4] * inv, o[i][5] * inv,
                                            o[i][6] * inv, o[i][7] * inv);
    }
}

// ---------------------------------------------------------------------------
// kernel_launch
// ---------------------------------------------------------------------------
extern "C" void kernel_launch(void* const* d_in, const int* in_sizes, int n_in,
                              void* d_out, int out_size) {
    const float* x     = (const float*)d_in[0];
    const float* w_qkv = (const float*)d_in[1];
    const float* w_out = (const float*)d_in[2];
    float* out = (float*)d_out;

    cudaFuncSetAttribute(attn_kernel, cudaFuncAttributeMaxDynamicSharedMemorySize,
                         ATTN_SMEM_FLOATS * (int)sizeof(float));

    // RoPE tables (consumed by the QKV epilogue)
    rope_tables_kernel<<<(S_LEN * (DKH / 2) + 255) / 256, 256>>>();

    // QKV projection with fused RoPE, scatter into g_q/g_k/g_v
    sgemm_nt<1><<<dim3(E3 / 128, MROWS / 128), 256>>>(x, w_qkv, nullptr,
                                                      MROWS, E3, KDIM);

    // causal flash attention -> g_attn (cp.async pipelined, 2 CTAs/SM)
    attn_kernel<<<dim3(S_LEN / 64, BHN), 256,
                  ATTN_SMEM_FLOATS * (int)sizeof(float)>>>();

    // output projection
    sgemm_nt<2><<<dim3(DMODEL / 128, MROWS / 128), 256>>>(nullptr, w_out, out,
                                                          MROWS, DMODEL, KDIM);
}